// round 3
// baseline (speedup 1.0000x reference)
#include <cuda_runtime.h>

// ComposeTransform: out[b] = trilinear(disp1[b], grid + disp2[b]) + disp2[b]
// vol per batch: [D,H,W,3], D=160, H=192, W=160, batch=2.
// One thread per (voxel, channel). Block = 384 threads = 128 voxels.
// d2 staged through smem with one coalesced float4 sweep (kills the 3
// redundant stride-12 global reads per thread from R2).

#define DD 160
#define HH 192
#define WW 160
#define VOX (DD * HH * WW)
#define TPB 384
#define VPB 128  // voxels per block

__global__ __launch_bounds__(TPB)
void compose_kernel(const float* __restrict__ d1,
                    const float* __restrict__ d2,
                    float* __restrict__ out)
{
    __shared__ float s_d2[TPB];

    int tid = threadIdx.x;
    int blk = blockIdx.x;

    // ---- stage this block's d2 span (384 floats) coalesced via float4 ----
    // n = 29,491,200 is an exact multiple of 384: no tail handling needed.
    if (tid < TPB / 4) {
        const float4* src = (const float4*)(d2 + (size_t)blk * TPB);
        ((float4*)s_d2)[tid] = src[tid];
    }
    __syncthreads();

    int lv = tid / 3;          // local voxel 0..127
    int ch = tid - lv * 3;     // channel 0..2

    int v = blk * VPB + lv;    // global voxel (includes batch)
    int b = v / VOX;
    int r = v - b * VOX;
    int x = r / (HH * WW);
    int rem = r - x * (HH * WW);
    int y = rem / WW;
    int z = rem - y * WW;

    float dx = s_d2[lv * 3 + 0];
    float dy = s_d2[lv * 3 + 1];
    float dz = s_d2[lv * 3 + 2];

    float lx = (float)x + dx;
    float ly = (float)y + dy;
    float lz = (float)z + dz;

    float fx = floorf(lx);
    float fy = floorf(ly);
    float fz = floorf(lz);

    // clipped floor / ceil corners (reference semantics)
    float i0x = fminf(fmaxf(fx, 0.0f), (float)(DD - 1));
    float i0y = fminf(fmaxf(fy, 0.0f), (float)(HH - 1));
    float i0z = fminf(fmaxf(fz, 0.0f), (float)(WW - 1));
    float i1x = fminf(fmaxf(fx + 1.0f, 0.0f), (float)(DD - 1));
    float i1y = fminf(fmaxf(fy + 1.0f, 0.0f), (float)(HH - 1));
    float i1z = fminf(fmaxf(fz + 1.0f, 0.0f), (float)(WW - 1));

    // weight attached to floor corner = clip(ceil_clipped - loc, 0, 1)
    float wfx = fminf(fmaxf(i1x - lx, 0.0f), 1.0f);
    float wfy = fminf(fmaxf(i1y - ly, 0.0f), 1.0f);
    float wfz = fminf(fmaxf(i1z - lz, 0.0f), 1.0f);
    float wcx = 1.0f - wfx;
    float wcy = 1.0f - wfy;
    float wcz = 1.0f - wfz;

    int ix0 = (int)i0x, iy0 = (int)i0y, iz0 = (int)i0z;
    int ix1 = (int)i1x, iy1 = (int)i1y, iz1 = (int)i1z;

    const float* vbase = d1 + (size_t)b * (size_t)VOX * 3 + ch;

    int row00 = (ix0 * HH + iy0) * WW;
    int row01 = (ix0 * HH + iy1) * WW;
    int row10 = (ix1 * HH + iy0) * WW;
    int row11 = (ix1 * HH + iy1) * WW;

    float w00z0 = wfx * wfy * wfz;
    float w00z1 = wfx * wfy * wcz;
    float w01z0 = wfx * wcy * wfz;
    float w01z1 = wfx * wcy * wcz;
    float w10z0 = wcx * wfy * wfz;
    float w10z1 = wcx * wfy * wcz;
    float w11z0 = wcx * wcy * wfz;
    float w11z1 = wcx * wcy * wcz;

    // independent loads, tree accumulation (shorter dependency chain)
    float g0 = __ldg(vbase + (size_t)(row00 + iz0) * 3);
    float g1 = __ldg(vbase + (size_t)(row00 + iz1) * 3);
    float g2 = __ldg(vbase + (size_t)(row01 + iz0) * 3);
    float g3 = __ldg(vbase + (size_t)(row01 + iz1) * 3);
    float g4 = __ldg(vbase + (size_t)(row10 + iz0) * 3);
    float g5 = __ldg(vbase + (size_t)(row10 + iz1) * 3);
    float g6 = __ldg(vbase + (size_t)(row11 + iz0) * 3);
    float g7 = __ldg(vbase + (size_t)(row11 + iz1) * 3);

    float p0 = fmaf(w00z1, g1, w00z0 * g0);
    float p1 = fmaf(w01z1, g3, w01z0 * g2);
    float p2 = fmaf(w10z1, g5, w10z0 * g4);
    float p3 = fmaf(w11z1, g7, w11z0 * g6);
    float acc = (p0 + p1) + (p2 + p3);

    out[(size_t)blk * TPB + tid] = acc + s_d2[tid];
}

extern "C" void kernel_launch(void* const* d_in, const int* in_sizes, int n_in,
                              void* d_out, int out_size) {
    const float* d1 = (const float*)d_in[0];
    const float* d2 = (const float*)d_in[1];
    float* out = (float*)d_out;
    int n = in_sizes[1];               // 29,491,200 = 76800 * 384
    int blocks = n / TPB;              // exact
    compose_kernel<<<blocks, TPB>>>(d1, d2, out);
}

// round 4
// speedup vs baseline: 1.1288x; 1.1288x over previous
#include <cuda_runtime.h>

// ComposeTransform: out[b] = trilinear(disp1[b], grid + disp2[b]) + disp2[b]
// vol per batch: [D,H,W,3], D=160, H=192, W=160, batch=2.
// One thread per (voxel, channel). Block = 480 threads = one full W-row
// (160 voxels x 3 channels). Grid = (H, D*B). All coordinates come from
// blockIdx -> no large integer divides; 32-bit offset math throughout.

#define DD 160
#define HH 192
#define WW 160
#define VOX (DD * HH * WW)
#define TPB (WW * 3)   // 480

__global__ __launch_bounds__(TPB)
void compose_kernel(const float* __restrict__ d1,
                    const float* __restrict__ d2,
                    float* __restrict__ out)
{
    const int tid = threadIdx.x;
    const int y   = blockIdx.x;          // 0..191
    const int xb  = blockIdx.y;          // 0..319  (= b*160 + x)
    const int b   = (xb >= DD) ? 1 : 0;
    const int x   = xb - b * DD;

    const int z  = tid * 0x5556 >> 16;   // tid/3 for tid<480 (0x5556*3=0x10002)
    const int ch = tid - z * 3;

    // row base (voxel units) for this (b,x,y) row; *3 for float offset
    const int rowv   = (xb * HH + y) * WW;      // includes batch: xb = b*DD+x
    const int rowf   = rowv * 3;                // float offset of row start

    // d2 components of this thread's voxel (stride-12 reads; warp-local L1 hits)
    const float* p2 = d2 + rowf + z * 3;
    float dx = __ldg(p2 + 0);
    float dy = __ldg(p2 + 1);
    float dz = __ldg(p2 + 2);

    float lx = (float)x + dx;
    float ly = (float)y + dy;
    float lz = (float)z + dz;

    float fx = floorf(lx);
    float fy = floorf(ly);
    float fz = floorf(lz);

    // clipped floor / ceil corners (reference semantics)
    float i0x = fminf(fmaxf(fx, 0.0f), (float)(DD - 1));
    float i0y = fminf(fmaxf(fy, 0.0f), (float)(HH - 1));
    float i0z = fminf(fmaxf(fz, 0.0f), (float)(WW - 1));
    float i1x = fminf(fmaxf(fx + 1.0f, 0.0f), (float)(DD - 1));
    float i1y = fminf(fmaxf(fy + 1.0f, 0.0f), (float)(HH - 1));
    float i1z = fminf(fmaxf(fz + 1.0f, 0.0f), (float)(WW - 1));

    // weight attached to floor corner = clip(ceil_clipped - loc, 0, 1)
    float wfx = fminf(fmaxf(i1x - lx, 0.0f), 1.0f);
    float wfy = fminf(fmaxf(i1y - ly, 0.0f), 1.0f);
    float wfz = fminf(fmaxf(i1z - lz, 0.0f), 1.0f);
    float wcx = 1.0f - wfx;
    float wcy = 1.0f - wfy;
    float wcz = 1.0f - wfz;

    int ix0 = (int)i0x, iy0 = (int)i0y, iz0 = (int)i0z;
    int ix1 = (int)i1x, iy1 = (int)i1y, iz1 = (int)i1z;

    const float* vbase = d1 + (size_t)b * (size_t)(VOX * 3) + ch;

    // 32-bit float offsets (max ~14.7M, fits easily)
    int row00 = (ix0 * HH + iy0) * (WW * 3);
    int row01 = (ix0 * HH + iy1) * (WW * 3);
    int row10 = (ix1 * HH + iy0) * (WW * 3);
    int row11 = (ix1 * HH + iy1) * (WW * 3);
    int z0 = iz0 * 3;
    int z1 = iz1 * 3;

    float w00z0 = wfx * wfy * wfz;
    float w00z1 = wfx * wfy * wcz;
    float w01z0 = wfx * wcy * wfz;
    float w01z1 = wfx * wcy * wcz;
    float w10z0 = wcx * wfy * wfz;
    float w10z1 = wcx * wfy * wcz;
    float w11z0 = wcx * wcy * wfz;
    float w11z1 = wcx * wcy * wcz;

    float g0 = __ldg(vbase + (row00 + z0));
    float g1 = __ldg(vbase + (row00 + z1));
    float g2 = __ldg(vbase + (row01 + z0));
    float g3 = __ldg(vbase + (row01 + z1));
    float g4 = __ldg(vbase + (row10 + z0));
    float g5 = __ldg(vbase + (row10 + z1));
    float g6 = __ldg(vbase + (row11 + z0));
    float g7 = __ldg(vbase + (row11 + z1));

    float p0 = fmaf(w00z1, g1, w00z0 * g0);
    float p1 = fmaf(w01z1, g3, w01z0 * g2);
    float p2r = fmaf(w10z1, g5, w10z0 * g4);
    float p3 = fmaf(w11z1, g7, w11z0 * g6);
    float acc = (p0 + p1) + (p2r + p3);

    // add this channel's d2 component
    float d2c = (ch == 0) ? dx : ((ch == 1) ? dy : dz);
    out[rowf + tid] = acc + d2c;
}

extern "C" void kernel_launch(void* const* d_in, const int* in_sizes, int n_in,
                              void* d_out, int out_size) {
    const float* d1 = (const float*)d_in[0];
    const float* d2 = (const float*)d_in[1];
    float* out = (float*)d_out;
    dim3 grid(HH, 2 * DD);   // (y, b*D + x)
    compose_kernel<<<grid, TPB>>>(d1, d2, out);
}

// round 6
// speedup vs baseline: 1.2036x; 1.0662x over previous
#include <cuda_runtime.h>

// ComposeTransform: out[b] = trilinear(disp1[b], grid + disp2[b]) + disp2[b]
// vol per batch: [D,H,W,3], D=160, H=192, W=160, batch=2.
// One thread per (voxel, channel), global-index mapping, block=256 for
// full 64-warp residency (8 blocks/SM vs 4 blocks at 384 threads).

#define DD 160
#define HH 192
#define WW 160
#define VOX (DD * HH * WW)

__global__ __launch_bounds__(256, 8)
void compose_kernel(const float* __restrict__ d1,
                    const float* __restrict__ d2,
                    float* __restrict__ out,
                    int n)  // total elements = voxels * 3
{
    int t = blockIdx.x * blockDim.x + threadIdx.x;
    if (t >= n) return;

    int v  = t / 3;          // voxel index (global, includes batch)
    int ch = t - v * 3;      // channel 0..2

    int b = v / VOX;
    int r = v - b * VOX;
    int x = r / (HH * WW);
    int rem = r - x * (HH * WW);
    int y = rem / WW;
    int z = rem - y * WW;

    // displacement 2 at this voxel (triplet lanes hit the same L1 lines)
    const float* pd2 = d2 + (size_t)v * 3;
    float dx = __ldg(pd2 + 0);
    float dy = __ldg(pd2 + 1);
    float dz = __ldg(pd2 + 2);

    float lx = (float)x + dx;
    float ly = (float)y + dy;
    float lz = (float)z + dz;

    float fx = floorf(lx);
    float fy = floorf(ly);
    float fz = floorf(lz);

    // clipped floor / ceil corners (reference semantics)
    float i0x = fminf(fmaxf(fx, 0.0f), (float)(DD - 1));
    float i0y = fminf(fmaxf(fy, 0.0f), (float)(HH - 1));
    float i0z = fminf(fmaxf(fz, 0.0f), (float)(WW - 1));
    float i1x = fminf(fmaxf(fx + 1.0f, 0.0f), (float)(DD - 1));
    float i1y = fminf(fmaxf(fy + 1.0f, 0.0f), (float)(HH - 1));
    float i1z = fminf(fmaxf(fz + 1.0f, 0.0f), (float)(WW - 1));

    // weight attached to floor corner = clip(ceil_clipped - loc, 0, 1)
    float wfx = fminf(fmaxf(i1x - lx, 0.0f), 1.0f);
    float wfy = fminf(fmaxf(i1y - ly, 0.0f), 1.0f);
    float wfz = fminf(fmaxf(i1z - lz, 0.0f), 1.0f);
    float wcx = 1.0f - wfx;
    float wcy = 1.0f - wfy;
    float wcz = 1.0f - wfz;

    int ix0 = (int)i0x, iy0 = (int)i0y, iz0 = (int)i0z;
    int ix1 = (int)i1x, iy1 = (int)i1y, iz1 = (int)i1z;

    const float* vbase = d1 + (size_t)b * (size_t)(VOX * 3) + ch;

    int row00 = (ix0 * HH + iy0) * (WW * 3);
    int row01 = (ix0 * HH + iy1) * (WW * 3);
    int row10 = (ix1 * HH + iy0) * (WW * 3);
    int row11 = (ix1 * HH + iy1) * (WW * 3);
    int z0 = iz0 * 3;
    int z1 = iz1 * 3;

    float w00z0 = wfx * wfy * wfz;
    float w00z1 = wfx * wfy * wcz;
    float w01z0 = wfx * wcy * wfz;
    float w01z1 = wfx * wcy * wcz;
    float w10z0 = wcx * wfy * wfz;
    float w10z1 = wcx * wfy * wcz;
    float w11z0 = wcx * wcy * wfz;
    float w11z1 = wcx * wcy * wcz;

    // independent loads, tree accumulation
    float g0 = __ldg(vbase + (row00 + z0));
    float g1 = __ldg(vbase + (row00 + z1));
    float g2 = __ldg(vbase + (row01 + z0));
    float g3 = __ldg(vbase + (row01 + z1));
    float g4 = __ldg(vbase + (row10 + z0));
    float g5 = __ldg(vbase + (row10 + z1));
    float g6 = __ldg(vbase + (row11 + z0));
    float g7 = __ldg(vbase + (row11 + z1));

    float q0 = fmaf(w00z1, g1, w00z0 * g0);
    float q1 = fmaf(w01z1, g3, w01z0 * g2);
    float q2 = fmaf(w10z1, g5, w10z0 * g4);
    float q3 = fmaf(w11z1, g7, w11z0 * g6);
    float acc = (q0 + q1) + (q2 + q3);

    // add this channel's d2 component
    float d2c = (ch == 0) ? dx : ((ch == 1) ? dy : dz);
    out[t] = acc + d2c;
}

extern "C" void kernel_launch(void* const* d_in, const int* in_sizes, int n_in,
                              void* d_out, int out_size) {
    const float* d1 = (const float*)d_in[0];
    const float* d2 = (const float*)d_in[1];
    float* out = (float*)d_out;
    int n = in_sizes[1];  // total elements (voxels * 3)
    int threads = 256;
    int blocks = (n + threads - 1) / threads;
    compose_kernel<<<blocks, threads>>>(d1, d2, out, n);
}

// round 7
// speedup vs baseline: 1.2070x; 1.0028x over previous
#include <cuda_runtime.h>

// ComposeTransform: out[b] = trilinear(disp1[b], grid + disp2[b]) + disp2[b]
// vol per batch: [D,H,W,3], D=160, H=192, W=160, batch=2.
// Persistent grid-stride kernel, 2 independent elements per loop iteration
// for 2x memory-level parallelism per warp.

#define DD 160
#define HH 192
#define WW 160
#define VOX (DD * HH * WW)

__device__ __forceinline__ float compose_one(const float* __restrict__ d1,
                                             const float* __restrict__ d2,
                                             int t)
{
    int v  = t / 3;          // voxel index (global, includes batch)
    int ch = t - v * 3;      // channel 0..2

    int b = v / VOX;
    int r = v - b * VOX;
    int x = r / (HH * WW);
    int rem = r - x * (HH * WW);
    int y = rem / WW;
    int z = rem - y * WW;

    const float* pd2 = d2 + (size_t)v * 3;
    float dx = __ldg(pd2 + 0);
    float dy = __ldg(pd2 + 1);
    float dz = __ldg(pd2 + 2);

    float lx = (float)x + dx;
    float ly = (float)y + dy;
    float lz = (float)z + dz;

    float fx = floorf(lx);
    float fy = floorf(ly);
    float fz = floorf(lz);

    float i0x = fminf(fmaxf(fx, 0.0f), (float)(DD - 1));
    float i0y = fminf(fmaxf(fy, 0.0f), (float)(HH - 1));
    float i0z = fminf(fmaxf(fz, 0.0f), (float)(WW - 1));
    float i1x = fminf(fmaxf(fx + 1.0f, 0.0f), (float)(DD - 1));
    float i1y = fminf(fmaxf(fy + 1.0f, 0.0f), (float)(HH - 1));
    float i1z = fminf(fmaxf(fz + 1.0f, 0.0f), (float)(WW - 1));

    float wfx = fminf(fmaxf(i1x - lx, 0.0f), 1.0f);
    float wfy = fminf(fmaxf(i1y - ly, 0.0f), 1.0f);
    float wfz = fminf(fmaxf(i1z - lz, 0.0f), 1.0f);
    float wcx = 1.0f - wfx;
    float wcy = 1.0f - wfy;
    float wcz = 1.0f - wfz;

    int ix0 = (int)i0x, iy0 = (int)i0y, iz0 = (int)i0z;
    int ix1 = (int)i1x, iy1 = (int)i1y, iz1 = (int)i1z;

    const float* vbase = d1 + (size_t)b * (size_t)(VOX * 3) + ch;

    int row00 = (ix0 * HH + iy0) * (WW * 3);
    int row01 = (ix0 * HH + iy1) * (WW * 3);
    int row10 = (ix1 * HH + iy0) * (WW * 3);
    int row11 = (ix1 * HH + iy1) * (WW * 3);
    int z0 = iz0 * 3;
    int z1 = iz1 * 3;

    float w00z0 = wfx * wfy * wfz;
    float w00z1 = wfx * wfy * wcz;
    float w01z0 = wfx * wcy * wfz;
    float w01z1 = wfx * wcy * wcz;
    float w10z0 = wcx * wfy * wfz;
    float w10z1 = wcx * wfy * wcz;
    float w11z0 = wcx * wcy * wfz;
    float w11z1 = wcx * wcy * wcz;

    float g0 = __ldg(vbase + (row00 + z0));
    float g1 = __ldg(vbase + (row00 + z1));
    float g2 = __ldg(vbase + (row01 + z0));
    float g3 = __ldg(vbase + (row01 + z1));
    float g4 = __ldg(vbase + (row10 + z0));
    float g5 = __ldg(vbase + (row10 + z1));
    float g6 = __ldg(vbase + (row11 + z0));
    float g7 = __ldg(vbase + (row11 + z1));

    float q0 = fmaf(w00z1, g1, w00z0 * g0);
    float q1 = fmaf(w01z1, g3, w01z0 * g2);
    float q2 = fmaf(w10z1, g5, w10z0 * g4);
    float q3 = fmaf(w11z1, g7, w11z0 * g6);
    float acc = (q0 + q1) + (q2 + q3);

    float d2c = (ch == 0) ? dx : ((ch == 1) ? dy : dz);
    return acc + d2c;
}

__global__ __launch_bounds__(256, 6)
void compose_kernel(const float* __restrict__ d1,
                    const float* __restrict__ d2,
                    float* __restrict__ out,
                    int n)
{
    const int stride = gridDim.x * blockDim.x;
    int t = blockIdx.x * blockDim.x + threadIdx.x;

    // main loop: two independent elements per iteration (2x MLP)
    for (; t + stride < n; t += 2 * stride) {
        float r0 = compose_one(d1, d2, t);
        float r1 = compose_one(d1, d2, t + stride);
        out[t] = r0;
        out[t + stride] = r1;
    }
    if (t < n) {
        out[t] = compose_one(d1, d2, t);
    }
}

extern "C" void kernel_launch(void* const* d_in, const int* in_sizes, int n_in,
                              void* d_out, int out_size) {
    const float* d1 = (const float*)d_in[0];
    const float* d2 = (const float*)d_in[1];
    float* out = (float*)d_out;
    int n = in_sizes[1];  // total elements (voxels * 3)
    int threads = 256;
    int blocks = 148 * 6;  // persistent: 6 blocks/SM * 148 SMs
    compose_kernel<<<blocks, threads>>>(d1, d2, out, n);
}